// round 6
// baseline (speedup 1.0000x reference)
#include <cuda_runtime.h>
#include <cuda_bf16.h>

#define P_     2
#define B_     96
#define A_     32
#define N_     (B_*A_)        // 3072
#define MD_    4
#define MA_    4
#define NPOLB_ 8
#define NPOL_  (B_*NPOLB_)    // 768
#define G_     8
#define ZCH_   3
#define CHUNK_ (N_/ZCH_)      // 1024 -> 4 iters of 256
#define NIT_   (CHUNK_/256)   // 4
#define QS_    512
#define NT_    24
#define C_LK_  0.0897935610625833f

typedef unsigned long long u64;

__device__ __forceinline__ u64 pk2(float lo, float hi) {
    u64 r; asm("mov.b64 %0,{%1,%2};" : "=l"(r) : "f"(lo), "f"(hi)); return r;
}
__device__ __forceinline__ void upk2(float& lo, float& hi, u64 v) {
    asm("mov.b64 {%0,%1},%2;" : "=f"(lo), "=f"(hi) : "l"(v));
}
__device__ __forceinline__ u64 add2(u64 a, u64 b) {
    u64 r; asm("add.rn.f32x2 %0,%1,%2;" : "=l"(r) : "l"(a), "l"(b)); return r;
}
__device__ __forceinline__ u64 mul2(u64 a, u64 b) {
    u64 r; asm("mul.rn.f32x2 %0,%1,%2;" : "=l"(r) : "l"(a), "l"(b)); return r;
}
__device__ __forceinline__ u64 fma2(u64 a, u64 b, u64 c) {
    u64 r; asm("fma.rn.f32x2 %0,%1,%2,%3;" : "=l"(r) : "l"(a), "l"(b), "l"(c)); return r;
}

struct __align__(16) Site {
    float x, y, z, ri;
    float cdg, inv_lami;
    float w0x, w0y;
    float w0z, w1x, w1y, w1z;
    int   b_i;
    unsigned pdmask;
    int   pad0, pad1;
};                                // 64B

struct __align__(16) SiteT {      // pose-independent, per-(block_type,k)
    int   a_i, o1, o2, pad;
    float k1, p0c, p0s, ri;
    float p1c, p1s, cdg, inv_lami;
    unsigned pdmask; int pad1, pad2, pad3;
};                                // 64B

__device__ ulonglong2 g_axy[P_*N_];    // {(-x,-x),(-y,-y)} (hydrogens poisoned)
__device__ u64        g_az [P_*N_];
__device__ float4     g_apos[P_*N_];   // x,y,z,rj (real coords)
__device__ float2     g_rjvol[P_*N_];  // rj, volj
__device__ SiteT      g_stab[NT_*G_];
__device__ double     g_acc[4];
__device__ int        g_done;

// ---------------------------------------------------------------------------
// Prep: blocks [0,24): atoms.  blocks [24,48): site-table (warp per entry).
// ---------------------------------------------------------------------------
__global__ void __launch_bounds__(256) prep_kernel(
    const float* __restrict__ coords,
    const int*   __restrict__ block_type,
    const int*   __restrict__ bonds,
    const int*   __restrict__ ranges,
    const int*   __restrict__ n_donH,
    const int*   __restrict__ n_acc,
    const int*   __restrict__ donH_inds,
    const int*   __restrict__ don_hvy_inds,
    const int*   __restrict__ acc_inds,
    const int*   __restrict__ hybrid,
    const int*   __restrict__ is_h,
    const float* __restrict__ lkp,
    const int*   __restrict__ pdist,
    const float* __restrict__ wg,
    const float* __restrict__ sp2t,
    const float* __restrict__ sp3t,
    const float* __restrict__ ringt)
{
    if (blockIdx.x < 24) {
        int t = blockIdx.x * 256 + threadIdx.x;
        if (t < 4) g_acc[t] = 0.0;
        if (t == 4) g_done = 0;
        int p  = t / N_;
        int j  = t - p*N_;
        int bj = j >> 5;
        int aj = j & 31;
        int bt = block_type[p*B_ + bj];
        const float* c = coords + (size_t)t*3;
        float x = c[0], y = c[1], z = c[2];
        float rj   = lkp[(bt*A_ + aj)*4 + 0];
        float volj = lkp[(bt*A_ + aj)*4 + 3];
        bool hyd = (is_h[bt*A_ + aj] != 0);
        float px = hyd ? 1.0e5f : -x;
        float py = hyd ? 1.0e5f : -y;
        float pz = hyd ? 1.0e5f : -z;
        ulonglong2 axy; axy.x = pk2(px, px); axy.y = pk2(py, py);
        g_axy[t] = axy;
        g_az[t]  = pk2(pz, pz);
        g_apos[t]  = make_float4(x, y, z, rj);
        g_rjvol[t] = make_float2(rj, hyd ? 0.f : volj);
        return;
    }

    int idx  = (blockIdx.x - 24) * 8 + (threadIdx.x >> 5);   // [0,192)
    int lane = threadIdx.x & 31;
    if (idx >= NT_*G_) return;
    int bt = idx >> 3;
    int k  = idx & 7;

    float wdist = wg[0], wang = wg[1];
    int a_i, o1 = 0, o2 = 0;
    float k1 = 0.f, p0c = 0.f, p0s = 0.f, p1c = 0.f, p1s = 0.f;
    bool mask;

    if (k < MD_) {
        mask = (k < n_donH[bt]);
        a_i = don_hvy_inds[bt*MD_ + k];
        o1  = donH_inds[bt*MD_ + k];
        k1  = wdist;
    } else {
        int kk = k - MD_;
        mask = (kk < n_acc[bt]);
        a_i = acc_inds[bt*MA_ + kk];
        int r1 = ranges[(bt*A_ + a_i)*2 + 0];
        o1     = bonds [(bt*A_ + r1)*2 + 1];
        int r2 = ranges[(bt*A_ + o1)*2 + 0];
        o2     = bonds [(bt*A_ + r2)*2 + 1];
        int hyb = hybrid[bt*MA_ + kk];
        const float* tor = (hyb == 0) ? sp2t : (hyb == 1) ? sp3t : ringt;
        float ct = cosf(wang), st = sinf(wang);
        k1 = -wdist*ct;
        float k2 = wdist*st;
        p0c = k2*cosf(tor[0]); p0s = k2*sinf(tor[0]);
        p1c = k2*cosf(tor[1]); p1s = k2*sinf(tor[1]);
    }

    int pd = pdist[(size_t)(bt*A_ + a_i)*A_ + lane];
    unsigned m = __ballot_sync(0xFFFFFFFFu, pd >= 4);

    if (lane == 0) {
        SiteT t;
        t.a_i = a_i; t.o1 = o1; t.o2 = o2; t.pad = 0;
        float ri   = lkp[(bt*A_ + a_i)*4 + 0];
        float dgi  = lkp[(bt*A_ + a_i)*4 + 1];
        float lami = lkp[(bt*A_ + a_i)*4 + 2];
        float invl = 1.f / lami;
        t.k1 = k1; t.p0c = p0c; t.p0s = p0s; t.ri = ri;
        t.p1c = p1c; t.p1s = p1s;
        t.cdg = mask ? (C_LK_ * dgi * invl) : 0.f;
        t.inv_lami = invl;
        t.pdmask = m; t.pad1 = t.pad2 = t.pad3 = 0;
        g_stab[idx] = t;
    }
}

// ---------------------------------------------------------------------------
// Fused: site build + packed filter (pre-validated hits) + coherent eval.
// grid (B_, P_, ZCH_), 256 threads, 4 blocks/SM.
// ---------------------------------------------------------------------------
__global__ void __launch_bounds__(256, 4) fused_kernel(
    const float* __restrict__ coords,
    const int*   __restrict__ block_type,
    const int*   __restrict__ msep,
    const float* __restrict__ lkg,
    float*       __restrict__ out)
{
    const int p    = blockIdx.y;
    const int b    = blockIdx.x;
    const int zb   = blockIdx.z * CHUNK_;
    const int tid  = threadIdx.x;
    const int w    = tid >> 5;
    const int lane = tid & 31;

    __shared__ Site     sh[G_];
    __shared__ unsigned q[G_][QS_];

    // ---- 96-bit inter-block separation mask (3 ballots, all warps same) ----
    unsigned sep0, sep1, sep2;
    {
        const int* row = msep + (p*B_ + b)*B_;
        sep0 = __ballot_sync(0xFFFFFFFFu, row[lane] >= 4);
        sep1 = __ballot_sync(0xFFFFFFFFu, row[lane + 32] >= 4);
        sep2 = __ballot_sync(0xFFFFFFFFu, row[lane + 64] >= 4);
    }

    // ---- site build: warp w builds site k=w from precomputed table ----
    {
        const int bt = block_type[p*B_ + b];
        SiteT t = g_stab[bt*G_ + w];
        const float* cb = coords + (size_t)((p*B_ + b)*A_) * 3;
        const float BIG = 1.0e4f;

        float px = cb[t.a_i*3+0], py = cb[t.a_i*3+1], pz = cb[t.a_i*3+2];
        float w0x, w0y, w0z, w1x, w1y, w1z;

        if (w < MD_) {
            float vx = cb[t.o1*3+0]-px, vy = cb[t.o1*3+1]-py, vz = cb[t.o1*3+2]-pz;
            float inv = rsqrtf(vx*vx + vy*vy + vz*vz + 1e-12f);
            float s = t.k1 * inv;
            w0x = px + s*vx; w0y = py + s*vy; w0z = pz + s*vz;
            w1x = w1y = w1z = BIG;
        } else {
            float bx = cb[t.o1*3+0], by = cb[t.o1*3+1], bz = cb[t.o1*3+2];
            float ax = cb[t.o2*3+0], ay = cb[t.o2*3+1], az = cb[t.o2*3+2];
            float e1x = px-bx, e1y = py-by, e1z = pz-bz;
            float inv = rsqrtf(e1x*e1x + e1y*e1y + e1z*e1z + 1e-12f);
            e1x *= inv; e1y *= inv; e1z *= inv;
            float ux = bx-ax, uy = by-ay, uz = bz-az;
            float nx = uy*e1z - uz*e1y;
            float ny = uz*e1x - ux*e1z;
            float nz = ux*e1y - uy*e1x;
            inv = rsqrtf(nx*nx + ny*ny + nz*nz + 1e-12f);
            nx *= inv; ny *= inv; nz *= inv;
            float e2x = ny*e1z - nz*e1y;
            float e2y = nz*e1x - nx*e1z;
            float e2z = nx*e1y - ny*e1x;
            w0x = px + t.k1*e1x + t.p0c*e2x + t.p0s*nx;
            w0y = py + t.k1*e1y + t.p0c*e2y + t.p0s*ny;
            w0z = pz + t.k1*e1z + t.p0c*e2z + t.p0s*nz;
            w1x = px + t.k1*e1x + t.p1c*e2x + t.p1s*nx;
            w1y = py + t.k1*e1y + t.p1c*e2y + t.p1s*ny;
            w1z = pz + t.k1*e1z + t.p1c*e2z + t.p1s*nz;
        }

        if (lane == 0) {
            Site s;
            s.x = px; s.y = py; s.z = pz; s.ri = t.ri;
            s.cdg = t.cdg; s.inv_lami = t.inv_lami;
            s.w0x = w0x; s.w0y = w0y; s.w0z = w0z;
            s.w1x = w1x; s.w1y = w1y; s.w1z = w1z;
            s.b_i = b; s.pdmask = t.pdmask;
            s.pad0 = 0; s.pad1 = 0;
            sh[w] = s;
        }
    }
    __syncthreads();

    // per-lane same-block gate: bit g = pdmask_g allows atom aj == lane
    unsigned sbm = 0;
    #pragma unroll
    for (int g = 0; g < G_; g++)
        sbm |= ((sh[g].pdmask >> lane) & 1u) << g;

    const float cutoff = lkg[0];
    const float ramp2  = lkg[1];
    const float d2low  = lkg[2];
    const float c2     = cutoff * cutoff;
    const float inv_r2 = 1.f / ramp2;
    const float thr_s  = (d2low + ramp2) * inv_r2;

    u64 sx2[4], sy2[4], sz2[4];
    #pragma unroll
    for (int h = 0; h < 4; h++) {
        sx2[h] = pk2(sh[2*h].x, sh[2*h+1].x);
        sy2[h] = pk2(sh[2*h].y, sh[2*h+1].y);
        sz2[h] = pk2(sh[2*h].z, sh[2*h+1].z);
    }

    float a0 = 0.f, a1 = 0.f;
    int qn = 0, qd = 0;
    const int base = p*N_ + zb;
    const unsigned lt = (1u << lane) - 1u;

    auto evalPair = [&](unsigned v) {           // pre-validated pair
        int g  = (int)(v >> 12);
        int jj = (int)(v & 4095u);
        const Site& s = sh[g];
        float4 a  = g_apos[p*N_ + jj];
        float2 rv = g_rjvol[p*N_ + jj];

        float dx = s.x - a.x, dy = s.y - a.y, dz = s.z - a.z;
        float d2 = fmaxf(dx*dx + dy*dy + dz*dz, 0.01f);
        float d  = sqrtf(d2);
        float xx = (d - (s.ri + rv.x)) * s.inv_lami;
        float lk = s.cdg * rv.y * __expf(-xx*xx) * __frcp_rn(d2);

        float ex = s.w0x - a.x, ey = s.w0y - a.y, ez = s.w0z - a.z;
        float dw0 = ex*ex + ey*ey + ez*ez;
        ex = s.w1x - a.x; ey = s.w1y - a.y; ez = s.w1z - a.z;
        float dw1 = ex*ex + ey*ey + ez*ez;
        float dwmin = fminf(dw0, dw1);

        float wt = __saturatef(fmaf(dwmin, -inv_r2, thr_s));
        float frac = wt*wt*(3.f - 2.f*wt);

        a0 += lk;
        a1 = fmaf(lk, frac, a1);
    };

    ulonglong2 axy = g_axy[base + tid];
    u64        az  = g_az [base + tid];

    #pragma unroll
    for (int it = 0; it < NIT_; it++) {
        ulonglong2 caxy = axy;
        u64        caz  = az;
        if (it + 1 < NIT_) {
            axy = g_axy[base + (it+1)*256 + tid];
            az  = g_az [base + (it+1)*256 + tid];
        }

        float d2s[8];
        #pragma unroll
        for (int h = 0; h < 4; h++) {
            u64 dx = add2(sx2[h], caxy.x);
            u64 dy = add2(sy2[h], caxy.y);
            u64 dz = add2(sz2[h], caz);
            u64 t  = mul2(dx, dx);
            t = fma2(dy, dy, t);
            t = fma2(dz, dz, t);
            upk2(d2s[2*h], d2s[2*h+1], t);
        }

        // warp-uniform atom-block for this iteration
        const int bj = (zb >> 5) + it*8 + w;
        unsigned gate;
        if (bj == b) gate = sbm;
        else {
            unsigned word = (bj < 32) ? sep0 : (bj < 64) ? sep1 : sep2;
            gate = ((word >> (bj & 31)) & 1u) ? 0xFFu : 0u;
        }

        unsigned hits = 0;
        #pragma unroll
        for (int g = 0; g < G_; g++)
            if (d2s[g] < c2) hits |= (1u << g);
        hits &= gate;
        int n = __popc(hits);

        unsigned b0 = __ballot_sync(0xFFFFFFFFu, n & 1);
        unsigned b1 = __ballot_sync(0xFFFFFFFFu, n & 2);
        unsigned b2 = __ballot_sync(0xFFFFFFFFu, n & 4);
        unsigned b3 = __ballot_sync(0xFFFFFFFFu, n & 8);
        int total = __popc(b0) + (__popc(b1) << 1) + (__popc(b2) << 2) + (__popc(b3) << 3);
        if (total == 0) continue;
        int excl = __popc(b0 & lt) + (__popc(b1 & lt) << 1)
                 + (__popc(b2 & lt) << 2) + (__popc(b3 & lt) << 3);

        int pos = qn + excl;
        const unsigned jj = (unsigned)(zb + it*256 + tid);
        unsigned h = hits;
        while (h) {
            int g = __ffs(h) - 1; h &= h - 1;
            q[w][pos & (QS_-1)] = ((unsigned)g << 12) | jj;
            pos++;
        }
        qn += total;

        if (qn - qd >= 32) {
            __syncwarp();
            do {
                unsigned v = q[w][(qd + lane) & (QS_-1)];
                evalPair(v);
                qd += 32;
            } while (qn - qd >= 32);
        }
    }

    {
        __syncwarp();
        int rem = qn - qd;
        if (lane < rem) {
            unsigned v = q[w][(qd + lane) & (QS_-1)];
            evalPair(v);
        }
    }

    #pragma unroll
    for (int off = 16; off > 0; off >>= 1) {
        a0 += __shfl_xor_sync(0xFFFFFFFFu, a0, off);
        a1 += __shfl_xor_sync(0xFFFFFFFFu, a1, off);
    }
    __shared__ float red0[8], red1[8];
    if (lane == 0) { red0[w] = a0; red1[w] = a1; }
    __syncthreads();
    if (tid == 0) {
        float t0 = 0.f, t1 = 0.f;
        #pragma unroll
        for (int i = 0; i < 8; i++) { t0 += red0[i]; t1 += red1[i]; }
        atomicAdd(&g_acc[0 + p], (double)t0);
        atomicAdd(&g_acc[2 + p], (double)t1);
        __threadfence();
        int done = atomicAdd(&g_done, 1);
        if (done == B_*P_*ZCH_ - 1) {
            #pragma unroll
            for (int i = 0; i < 4; i++)
                out[i] = (float)atomicAdd(&g_acc[i], 0.0);
        }
    }
}

extern "C" void kernel_launch(void* const* d_in, const int* in_sizes, int n_in,
                              void* d_out, int out_size) {
    const float* coords       = (const float*)d_in[0];
    const int*   block_type   = (const int*)  d_in[1];
    const int*   msep         = (const int*)  d_in[2];
    const int*   bonds        = (const int*)  d_in[4];
    const int*   ranges       = (const int*)  d_in[5];
    const int*   n_donH       = (const int*)  d_in[6];
    const int*   n_acc        = (const int*)  d_in[7];
    const int*   donH_inds    = (const int*)  d_in[8];
    const int*   don_hvy_inds = (const int*)  d_in[9];
    const int*   acc_inds     = (const int*)  d_in[10];
    const int*   hybrid       = (const int*)  d_in[11];
    const int*   is_h         = (const int*)  d_in[12];
    const float* lkp          = (const float*)d_in[13];
    const int*   pdist        = (const int*)  d_in[14];
    const float* lkg          = (const float*)d_in[15];
    const float* wg           = (const float*)d_in[16];
    const float* sp2t         = (const float*)d_in[17];
    const float* sp3t         = (const float*)d_in[18];
    const float* ringt        = (const float*)d_in[19];

    prep_kernel<<<48, 256>>>(
        coords, block_type, bonds, ranges, n_donH, n_acc,
        donH_inds, don_hvy_inds, acc_inds, hybrid, is_h,
        lkp, pdist, wg, sp2t, sp3t, ringt);

    dim3 grid(B_, P_, ZCH_);
    fused_kernel<<<grid, 256>>>(coords, block_type, msep, lkg, (float*)d_out);
}